// round 14
// baseline (speedup 1.0000x reference)
#include <cuda_runtime.h>
#include <cuda_bf16.h>
#include <cstdint>
#include <math.h>

// ---------------------------------------------------------------------------
// TinyTransformer — fused 3-pass bf16-split mma GEMM (R12 pipeline: NSTG=5,
// CP_WAIT(2), 1 CTA/SM; wrap-pointer slot addressing) + simplified-softmax
// mma attention with register-resident K. sm_103a.
// ---------------------------------------------------------------------------

#define TT      1024
#define BB      4
#define DD      1024
#define HH      16
#define DQKV    64
#define FFD     4096
#define HD      1024
#define NR      4096
#define NLAYERS 4
#define EPSV    1e-6f

typedef unsigned short u16;
typedef unsigned int   u32;
typedef unsigned long long u64;

// ------------------------- scratch (no allocations) ------------------------
__device__ float g_x[(size_t)NR * DD];
__device__ float g_z[(size_t)NR * DD];
__device__ float g_f[(size_t)NR * DD];

__device__ u16 g_xh[(size_t)NR * DD], g_xl[(size_t)NR * DD];
__device__ u16 g_hh[(size_t)NR * FFD], g_hl[(size_t)NR * FFD];
__device__ u16 g_zh[(size_t)NR * DD], g_zl[(size_t)NR * DD];
__device__ u16 g_kqvh[(size_t)NR * 3 * HD], g_kqvl[(size_t)NR * 3 * HD];
__device__ float g_bqkv[(size_t)NLAYERS * 3 * HD];

#define WPL ((size_t)FFD * DD * 2 + (size_t)3 * HD * DD)
__device__ u16 g_wh[(size_t)NLAYERS * WPL];
__device__ u16 g_wl[(size_t)NLAYERS * WPL];

// ---------------------------- helpers --------------------------------------
__device__ __forceinline__ u32 smem_u32(const void* p) {
    u32 a;
    asm("{ .reg .u64 t; cvta.to.shared.u64 t, %1; cvt.u32.u64 %0, t; }"
        : "=r"(a) : "l"(p));
    return a;
}
__device__ __forceinline__ u16 bf_hi(float v) {
    return __bfloat16_as_ushort(__float2bfloat16(v));
}
__device__ __forceinline__ u16 bf_lo(float v, u16 hi) {
    float r = v - __bfloat162float(__ushort_as_bfloat16(hi));
    return __bfloat16_as_ushort(__float2bfloat16(r));
}
__device__ __forceinline__ u32 pk2(float a, float b) {
    __nv_bfloat162 t = __floats2bfloat162_rn(a, b);
    return *(u32*)&t;
}
__device__ __forceinline__ float pk_lo_f(u32 p) {
    return __bfloat162float(((__nv_bfloat162*)&p)->x);
}
__device__ __forceinline__ float pk_hi_f(u32 p) {
    return __bfloat162float(((__nv_bfloat162*)&p)->y);
}
__device__ __forceinline__ void cp16(u32 dst, const void* src) {
    asm volatile("cp.async.cg.shared.global [%0], [%1], 16;"
                 :: "r"(dst), "l"(src) : "memory");
}
#define CP_COMMIT() asm volatile("cp.async.commit_group;" ::: "memory")
#define CP_WAIT(n)  asm volatile("cp.async.wait_group %0;" :: "n"(n) : "memory")

__device__ __forceinline__ void ldsm4(u32* r, u32 a) {
    asm volatile("ldmatrix.sync.aligned.m8n8.x4.shared.b16 {%0,%1,%2,%3}, [%4];"
                 : "=r"(r[0]), "=r"(r[1]), "=r"(r[2]), "=r"(r[3]) : "r"(a));
}
__device__ __forceinline__ void ldsm4t(u32* r, u32 a) {
    asm volatile("ldmatrix.sync.aligned.m8n8.x4.trans.shared.b16 {%0,%1,%2,%3}, [%4];"
                 : "=r"(r[0]), "=r"(r[1]), "=r"(r[2]), "=r"(r[3]) : "r"(a));
}
__device__ __forceinline__ void mma_bf16(float* c, const u32* a, u32 b0, u32 b1) {
    asm volatile(
        "mma.sync.aligned.m16n8k16.row.col.f32.bf16.bf16.f32 "
        "{%0,%1,%2,%3}, {%4,%5,%6,%7}, {%8,%9}, {%0,%1,%2,%3};"
        : "+f"(c[0]), "+f"(c[1]), "+f"(c[2]), "+f"(c[3])
        : "r"(a[0]), "r"(a[1]), "r"(a[2]), "r"(a[3]), "r"(b0), "r"(b1));
}

// --------------------------- fused mma GEMM --------------------------------
// CTA 128x128, BK=32, 8 warps (2m x 4n), warp tile 64x32, 1 CTA/SM.
// NSTG=5, CP_WAIT(2): stages i and i+1 always resident (R9/R12 pipeline).
// Slot addressing via wrapping pointers (no per-iter mod/div).
#define NSTG     5
#define TILE_M   128
#define TILE_N   128
#define TILE_K   32
#define TILE_SZ  (TILE_M * TILE_K * 2)    // 8 KB per operand tile
#define STAGE_SZ (4 * TILE_SZ)            // 32 KB: Ah|Al|Bh|Bl
#define EPI_PAD  132
#define GEMM_SMEM (NSTG * STAGE_SZ)       // 160 KB (> epi 67.6 KB)

__device__ __forceinline__ u32 tile_addr(u32 base, int r, int seg) {
    return base + r * 64 + ((seg ^ ((r >> 1) & 3)) << 4);
}

// MODE 0: fp32 C; MODE 1: bf16 hi/lo split. SCALEK: scale cols < HD by 1/32.
template <bool RELU, int MODE, bool SCALEK>
__global__ void __launch_bounds__(256, 1)
gemm_mma(const u16* __restrict__ Ah, const u16* __restrict__ Al,
         const u16* __restrict__ Bh, const u16* __restrict__ Bl,
         const float* __restrict__ bias,
         float* __restrict__ C, u16* __restrict__ Chi, u16* __restrict__ Clo,
         int M, int N, int K)
{
    extern __shared__ __align__(1024) char smem[];
    const u32 sbase = smem_u32(smem);
    const u32 send = sbase + NSTG * STAGE_SZ;

    const int tid = threadIdx.x;
    const int wid = tid >> 5, lane = tid & 31;
    const int wm = wid >> 2, wn = wid & 3;
    const int m0 = blockIdx.y * TILE_M;
    const int n0 = blockIdx.x * TILE_N;

    const int NITER = K / TILE_K;

    const int cr0 = tid >> 2, csg = tid & 3;
    const size_t gofs0 = (size_t)cr0 * K + csg * 8;
    const size_t gofs1 = gofs0 + (size_t)64 * K;
    const u32 sofs0 = tile_addr(0, cr0, csg);
    const u32 sofs1 = tile_addr(0, cr0 + 64, csg);

    auto load_stage = [&](int kc, u32 st) {
        const size_t ab = (size_t)m0 * K + (size_t)kc * TILE_K;
        const size_t bb = (size_t)n0 * K + (size_t)kc * TILE_K;
        cp16(st + sofs0, Ah + ab + gofs0);
        cp16(st + sofs1, Ah + ab + gofs1);
        cp16(st + TILE_SZ + sofs0, Al + ab + gofs0);
        cp16(st + TILE_SZ + sofs1, Al + ab + gofs1);
        cp16(st + 2 * TILE_SZ + sofs0, Bh + bb + gofs0);
        cp16(st + 2 * TILE_SZ + sofs1, Bh + bb + gofs1);
        cp16(st + 3 * TILE_SZ + sofs0, Bl + bb + gofs0);
        cp16(st + 3 * TILE_SZ + sofs1, Bl + bb + gofs1);
        CP_COMMIT();
    };

    float acc[4][4][4];
#pragma unroll
    for (int i = 0; i < 4; i++)
#pragma unroll
        for (int j = 0; j < 4; j++)
#pragma unroll
            for (int t = 0; t < 4; t++) acc[i][j][t] = 0.f;

    const int lrow = lane & 15;
    const int lseg = lane >> 4;
    u32 aoff[2][4], boff[2][2];
#pragma unroll
    for (int ks = 0; ks < 2; ks++) {
#pragma unroll
        for (int ma = 0; ma < 4; ma++)
            aoff[ks][ma] = tile_addr(0, wm * 64 + ma * 16 + lrow, 2 * ks + lseg);
#pragma unroll
        for (int np = 0; np < 2; np++)
            boff[ks][np] = tile_addr(0, wn * 32 + np * 16 + lrow, 2 * ks + lseg);
    }

    u32 fah[2][4][4], fal[2][4][4], fbh[2][2][4], fbl[2][2][4];

    auto ldfrags = [&](int buf, u32 st, int ks) {
#pragma unroll
        for (int ma = 0; ma < 4; ma++) {
            ldsm4(fah[buf][ma], st + aoff[ks][ma]);
            ldsm4(fal[buf][ma], st + TILE_SZ + aoff[ks][ma]);
        }
#pragma unroll
        for (int np = 0; np < 2; np++) {
            ldsm4(fbh[buf][np], st + 2 * TILE_SZ + boff[ks][np]);
            ldsm4(fbl[buf][np], st + 3 * TILE_SZ + boff[ks][np]);
        }
    };
    auto mma_all = [&](int buf) {
#pragma unroll
        for (int ma = 0; ma < 4; ma++)
#pragma unroll
            for (int na = 0; na < 4; na++)
                mma_bf16(acc[ma][na], fah[buf][ma],
                         fbh[buf][na >> 1][na & 1], fbh[buf][na >> 1][(na & 1) + 2]);
#pragma unroll
        for (int ma = 0; ma < 4; ma++)
#pragma unroll
            for (int na = 0; na < 4; na++)
                mma_bf16(acc[ma][na], fah[buf][ma],
                         fbl[buf][na >> 1][na & 1], fbl[buf][na >> 1][(na & 1) + 2]);
#pragma unroll
        for (int ma = 0; ma < 4; ma++)
#pragma unroll
            for (int na = 0; na < 4; na++)
                mma_bf16(acc[ma][na], fal[buf][ma],
                         fbh[buf][na >> 1][na & 1], fbh[buf][na >> 1][(na & 1) + 2]);
    };

    // prologue: preload stages 0..3 (slots 0..3); wait -> 0,1,2 complete
    for (int s = 0; s < NSTG - 1 && s < NITER; s++)
        load_stage(s, sbase + s * STAGE_SZ);
    CP_WAIT(2);
    __syncthreads();
    ldfrags(0, sbase, 0);

    u32 stc = sbase;                        // slot of stage i
    u32 stl = sbase + (NSTG - 1) * STAGE_SZ;  // slot of stage i+4 (to load)

    for (int i = 0; i < NITER; i++) {
        if (i + NSTG - 1 < NITER) {
            load_stage(i + NSTG - 1, stl);
            stl += STAGE_SZ;
            if (stl == send) stl = sbase;
        }
        u32 stn = stc + STAGE_SZ;
        if (stn == send) stn = sbase;

        ldfrags(1, stc, 1);
        mma_all(0);
        if (i + 1 < NITER) ldfrags(0, stn, 0);
        mma_all(1);

        CP_WAIT(2);
        __syncthreads();
        stc = stn;
    }
    CP_WAIT(0);
    __syncthreads();

    // ---- epilogue ----
    float (*buf)[EPI_PAD] = (float (*)[EPI_PAD])smem;
    const int qr = lane >> 2, qc = (lane & 3) << 1;
#pragma unroll
    for (int ma = 0; ma < 4; ma++)
#pragma unroll
        for (int na = 0; na < 4; na++) {
            const int r = wm * 64 + ma * 16 + qr;
            const int c = wn * 32 + na * 8 + qc;
            buf[r][c]     = acc[ma][na][0];
            buf[r][c + 1] = acc[ma][na][1];
            buf[r + 8][c]     = acc[ma][na][2];
            buf[r + 8][c + 1] = acc[ma][na][3];
        }
    __syncthreads();

#pragma unroll
    for (int u = 0; u < 16; u++) {
        const int idx = tid + u * 256;
        const int r = idx >> 5, c4 = (idx & 31) << 2;
        const int col = n0 + c4;
        float4 v = *(float4*)&buf[r][c4];
        v.x += bias[col]; v.y += bias[col + 1];
        v.z += bias[col + 2]; v.w += bias[col + 3];
        if (RELU) {
            v.x = fmaxf(v.x, 0.f); v.y = fmaxf(v.y, 0.f);
            v.z = fmaxf(v.z, 0.f); v.w = fmaxf(v.w, 0.f);
        }
        if (SCALEK && col < HD) {
            v.x *= 0.03125f; v.y *= 0.03125f;
            v.z *= 0.03125f; v.w *= 0.03125f;
        }
        const size_t o = (size_t)(m0 + r) * N + col;
        if (MODE == 0) {
            *(float4*)(C + o) = v;
        } else {
            ushort4 hh4, ll4;
            hh4.x = bf_hi(v.x); ll4.x = bf_lo(v.x, hh4.x);
            hh4.y = bf_hi(v.y); ll4.y = bf_lo(v.y, hh4.y);
            hh4.z = bf_hi(v.z); ll4.z = bf_lo(v.z, hh4.z);
            hh4.w = bf_hi(v.w); ll4.w = bf_lo(v.w, hh4.w);
            *(ushort4*)(Chi + o) = hh4;
            *(ushort4*)(Clo + o) = ll4;
        }
    }
}

// --------------- prep: ALL weight transposes + bias pack (1 launch) --------
#define PREP_PL   11264
#define PREP_TRB  (NLAYERS * PREP_PL)
#define PREP_BLK  (PREP_TRB + 48)

__global__ void __launch_bounds__(256)
prep_all(const float* __restrict__ W1, const float* __restrict__ W2,
         const float* __restrict__ Wk, const float* __restrict__ Wq,
         const float* __restrict__ Wv,
         const float* __restrict__ bk, const float* __restrict__ bq,
         const float* __restrict__ bv,
         u16* __restrict__ wh, u16* __restrict__ wl, float* __restrict__ gb)
{
    const int bid = blockIdx.x;
    const int tid = threadIdx.x;

    if (bid >= PREP_TRB) {
        const int i = (bid - PREP_TRB) * 256 + tid;
        const int l = i / (3 * HD), c = i % (3 * HD);
        const float* s = (c < HD) ? bk : ((c < 2 * HD) ? bq : bv);
        gb[i] = s[l * HD + (c & (HD - 1))];
        return;
    }

    const int l = bid / PREP_PL;
    int t = bid % PREP_PL;
    const float* W;
    u16 *Th, *Tl;
    int K, N;
    const size_t wb = (size_t)l * WPL;
    if (t < 4096) {
        W = W1 + (size_t)l * DD * FFD; K = DD; N = FFD;
        Th = wh + wb; Tl = wl + wb;
    } else if (t < 8192) {
        t -= 4096;
        W = W2 + (size_t)l * FFD * DD; K = FFD; N = DD;
        Th = wh + wb + (size_t)FFD * DD; Tl = wl + wb + (size_t)FFD * DD;
    } else {
        t -= 8192;
        const int m = t >> 10; t &= 1023;
        const float* Wm = (m == 0) ? Wk : ((m == 1) ? Wq : Wv);
        W = Wm + (size_t)l * DD * HD; K = DD; N = HD;
        const size_t o = 2 * (size_t)FFD * DD + (size_t)m * HD * DD;
        Th = wh + wb + o; Tl = wl + wb + o;
    }
    const int nx = N >> 5;
    const int n0 = (t % nx) << 5, k0 = (t / nx) << 5;

    __shared__ float tb[32][33];
    const int tx = tid & 31, ty = tid >> 5;
#pragma unroll
    for (int i = 0; i < 4; i++)
        tb[ty + i * 8][tx] = W[(size_t)(k0 + ty + i * 8) * N + n0 + tx];
    __syncthreads();

    const int n = tid >> 3;
    const int kk = (tid & 7) << 2;
    u16 hx[4], lx[4];
#pragma unroll
    for (int j = 0; j < 4; j++) {
        const float v = tb[kk + j][n];
        hx[j] = bf_hi(v);
        lx[j] = bf_lo(v, hx[j]);
    }
    const size_t o = (size_t)(n0 + n) * K + k0 + kk;
    *(ushort4*)(Th + o) = make_ushort4(hx[0], hx[1], hx[2], hx[3]);
    *(ushort4*)(Tl + o) = make_ushort4(lx[0], lx[1], lx[2], lx[3]);
}

__global__ void __launch_bounds__(256)
split_act(const float* __restrict__ X, u16* __restrict__ Xh,
          u16* __restrict__ Xl, int n4)
{
    const int i = blockIdx.x * 256 + threadIdx.x;
    if (i >= n4) return;
    const float4 v = ((const float4*)X)[i];
    ushort4 h, l;
    h.x = bf_hi(v.x); l.x = bf_lo(v.x, h.x);
    h.y = bf_hi(v.y); l.y = bf_lo(v.y, h.y);
    h.z = bf_hi(v.z); l.z = bf_lo(v.z, h.z);
    h.w = bf_hi(v.w); l.w = bf_lo(v.w, h.w);
    ((ushort4*)Xh)[i] = h;
    ((ushort4*)Xl)[i] = l;
}

// ------------------------------ resnorm ------------------------------------
template <bool SPLIT>
__global__ void __launch_bounds__(256)
resnorm_kernel(const float* __restrict__ X, const float* __restrict__ FX,
               float* __restrict__ OUT, u16* __restrict__ Oh, u16* __restrict__ Ol)
{
    __shared__ float red[8], red2[8], stat[2];
    const int tid = threadIdx.x;
    const int w = tid >> 5, lane = tid & 31;
    const size_t off = (size_t)blockIdx.x * DD;

    const float4 xv = ((const float4*)(X + off))[tid];
    const float4 fv = ((const float4*)(FX + off))[tid];
    const float y0 = xv.x + fv.x, y1 = xv.y + fv.y;
    const float y2 = xv.z + fv.z, y3 = xv.w + fv.w;

    float s = y0 + y1 + y2 + y3;
    float sq = y0 * y0 + y1 * y1 + y2 * y2 + y3 * y3;
#pragma unroll
    for (int o = 16; o; o >>= 1) {
        s += __shfl_xor_sync(0xFFFFFFFFu, s, o);
        sq += __shfl_xor_sync(0xFFFFFFFFu, sq, o);
    }
    if (lane == 0) { red[w] = s; red2[w] = sq; }
    __syncthreads();
    if (tid == 0) {
        float S = 0.f, Q = 0.f;
#pragma unroll
        for (int i = 0; i < 8; i++) { S += red[i]; Q += red2[i]; }
        const float mu = S * (1.0f / DD);
        const float var = fmaxf((Q - (float)DD * mu * mu) * (1.0f / (DD - 1)), 0.0f);
        stat[0] = mu;
        stat[1] = 1.0f / (sqrtf(var) + EPSV);
    }
    __syncthreads();
    const float mu = stat[0], inv = stat[1];
    const float4 o = make_float4((y0 - mu) * inv, (y1 - mu) * inv,
                                 (y2 - mu) * inv, (y3 - mu) * inv);
    ((float4*)(OUT + off))[tid] = o;
    if (SPLIT) {
        ushort4 h, l;
        h.x = bf_hi(o.x); l.x = bf_lo(o.x, h.x);
        h.y = bf_hi(o.y); l.y = bf_lo(o.y, h.y);
        h.z = bf_hi(o.z); l.z = bf_lo(o.z, h.z);
        h.w = bf_hi(o.w); l.w = bf_lo(o.w, h.w);
        ((ushort4*)(Oh + off))[tid] = h;
        ((ushort4*)(Ol + off))[tid] = l;
    }
}

// ----------------------- mma flash attention --------------------------------
#define ASTR  72
#define ATSZ  (64 * ASTR)
#define ATT_SMEM ((2 + 8) * ATSZ * 2)

__global__ void __launch_bounds__(128, 2)
attn_mma(const u16* __restrict__ kqvh, const u16* __restrict__ kqvl,
         float* __restrict__ Ob)
{
    extern __shared__ __align__(128) u16 asm_[];
    u16* Kh = asm_;
    u16* Kl = asm_ + ATSZ;
    u16* stg = asm_ + 2 * ATSZ;

    const int tid = threadIdx.x;
    const int wid = tid >> 5, lane = tid & 31;
    const int bh = blockIdx.y;
    const int b = bh >> 4, h = bh & 15;
    const int i0 = blockIdx.x * 64;
    const int colK = h * DQKV;

#pragma unroll
    for (int k = 0; k < 8; k++) {
        const int c = tid + k * 128;
        const int hi = (c < 512);
        const int idx = c & 511;
        const int r = idx >> 3, ch = idx & 7;
        const u16* src = (hi ? kqvh : kqvl) +
                         (size_t)((i0 + r) * BB + b) * (3 * HD) + colK + ch * 8;
        u16* dst = (hi ? Kh : Kl) + r * ASTR + ch * 8;
        cp16(smem_u32(dst), src);
    }

    auto load_stage = [&](int j0, int s) {
        u16* base = stg + s * 4 * ATSZ;
#pragma unroll
        for (int k = 0; k < 16; k++) {
            const int c = tid + k * 128;
            const int sel = c >> 9;
            const int idx = c & 511;
            const int r = idx >> 3, ch = idx & 7;
            const u16* sp = (sel & 1) ? kqvl : kqvh;
            const int cb = (sel >> 1) ? 2 * HD : HD;
            cp16(smem_u32(base + sel * ATSZ + r * ASTR + ch * 8),
                 sp + (size_t)((j0 + r) * BB + b) * (3 * HD) + cb + colK + ch * 8);
        }
    };

    load_stage(0, 0);
    CP_COMMIT();

    float l0 = 0.f, l1 = 0.f;
    float o[8][4];
#pragma unroll
    for (int a = 0; a < 8; a++)
#pragma unroll
        for (int q = 0; q < 4; q++) o[a][q] = 0.f;

    const int r16 = lane & 15;
    const int kh8 = (lane >> 4) << 3;
    const int g = lane >> 3;
    const int vrow = ((g & 1) << 3) + (lane & 7);
    const int vcol = (g >> 1) << 3;

    u32 kfh[4][4], kfl[4][4];

    for (int jt = 0; jt < TT / 64; jt++) {
        if (jt + 1 < TT / 64) {
            load_stage((jt + 1) * 64, (jt + 1) & 1);
            CP_COMMIT();
            CP_WAIT(1);
        } else {
            CP_WAIT(0);
        }
        __syncthreads();

        if (jt == 0) {
#pragma unroll
            for (int t = 0; t < 4; t++) {
                ldsm4(kfh[t], smem_u32(Kh + (wid * 16 + r16) * ASTR + t * 16 + kh8));
                ldsm4(kfl[t], smem_u32(Kl + (wid * 16 + r16) * ASTR + t * 16 + kh8));
            }
        }

        u16* sb = stg + (jt & 1) * 4 * ATSZ;
        u16* Qh = sb;
        u16* Ql = sb + ATSZ;
        u16* Vh = sb + 2 * ATSZ;
        u16* Vl = sb + 3 * ATSZ;

        float sc[8][4];
#pragma unroll
        for (int a = 0; a < 8; a++)
#pragma unroll
            for (int q = 0; q < 4; q++) sc[a][q] = 0.f;

#pragma unroll
        for (int t = 0; t < 4; t++) {
#pragma unroll
            for (int jb = 0; jb < 4; jb++) {
                u32 qh[4], ql[4];
                ldsm4(qh, smem_u32(Qh + (jb * 16 + r16) * ASTR + t * 16 + kh8));
                ldsm4(ql, smem_u32(Ql + (jb * 16 + r16) * ASTR + t * 16 + kh8));
#pragma unroll
                for (int sel = 0; sel < 2; sel++) {
                    const int a = jb * 2 + sel;
                    mma_bf16(sc[a], kfh[t], qh[sel], qh[sel + 2]);
                    mma_bf16(sc[a], kfl[t], qh[sel], qh[sel + 2]);
                    mma_bf16(sc[a], kfh[t], ql[sel], ql[sel + 2]);
                }
            }
        }

        float ps0 = 0.f, ps1 = 0.f;
#pragma unroll
        for (int a = 0; a < 8; a++) {
            sc[a][0] = __expf(sc[a][0]); ps0 += sc[a][0];
            sc[a][1] = __expf(sc[a][1]); ps0 += sc[a][1];
            sc[a][2] = __expf(sc[a][2]); ps1 += sc[a][2];
            sc[a][3] = __expf(sc[a][3]); ps1 += sc[a][3];
        }
        ps0 += __shfl_xor_sync(0xFFFFFFFFu, ps0, 1);
        ps0 += __shfl_xor_sync(0xFFFFFFFFu, ps0, 2);
        ps1 += __shfl_xor_sync(0xFFFFFFFFu, ps1, 1);
        ps1 += __shfl_xor_sync(0xFFFFFFFFu, ps1, 2);
        l0 += ps0;
        l1 += ps1;

#pragma unroll
        for (int t = 0; t < 4; t++) {
            u32 ph[4], pl[4];
            ph[0] = pk2(sc[2 * t][0], sc[2 * t][1]);
            ph[1] = pk2(sc[2 * t][2], sc[2 * t][3]);
            ph[2] = pk2(sc[2 * t + 1][0], sc[2 * t + 1][1]);
            ph[3] = pk2(sc[2 * t + 1][2], sc[2 * t + 1][3]);
            pl[0] = pk2(sc[2 * t][0] - pk_lo_f(ph[0]), sc[2 * t][1] - pk_hi_f(ph[0]));
            pl[1] = pk2(sc[2 * t][2] - pk_lo_f(ph[1]), sc[2 * t][3] - pk_hi_f(ph[1]));
            pl[2] = pk2(sc[2 * t + 1][0] - pk_lo_f(ph[2]), sc[2 * t + 1][1] - pk_hi_f(ph[2]));
            pl[3] = pk2(sc[2 * t + 1][2] - pk_lo_f(ph[3]), sc[2 * t + 1][3] - pk_hi_f(ph[3]));
#pragma unroll
            for (int dq = 0; dq < 4; dq++) {
                u32 vh4[4], vl4[4];
                const u32 va = (t * 16 + vrow) * ASTR + dq * 16 + vcol;
                ldsm4t(vh4, smem_u32(Vh + va));
                ldsm4t(vl4, smem_u32(Vl + va));
#pragma unroll
                for (int sel = 0; sel < 2; sel++) {
                    const int a = dq * 2 + sel;
                    mma_bf16(o[a], ph, vh4[2 * sel], vh4[2 * sel + 1]);
                    mma_bf16(o[a], pl, vh4[2 * sel], vh4[2 * sel + 1]);
                    mma_bf16(o[a], ph, vl4[2 * sel], vl4[2 * sel + 1]);
                }
            }
        }
        __syncthreads();
    }

    const float inv0 = 1.0f / l0, inv1 = 1.0f / l1;
    const int lr = lane >> 2;
    const int row0 = i0 + wid * 16 + lr;
#pragma unroll
    for (int a = 0; a < 8; a++) {
        const int d = a * 8 + ((lane & 3) << 1);
        const size_t o0 = (size_t)(row0 * BB + b) * HD + colK + d;
        const size_t o1 = (size_t)((row0 + 8) * BB + b) * HD + colK + d;
        *(float2*)(Ob + o0) = make_float2(o[a][0] * inv0, o[a][1] * inv0);
        *(float2*)(Ob + o1) = make_float2(o[a][2] * inv1, o[a][3] * inv1);
    }
}

// ----------------------------- launcher ------------------------------------
extern "C" void kernel_launch(void* const* d_in, const int* in_sizes, int n_in,
                              void* d_out, int out_size)
{
    (void)in_sizes; (void)n_in; (void)out_size;
    const float* x  = (const float*)d_in[0];
    const float* Wk = (const float*)d_in[2];
    const float* bk = (const float*)d_in[3];
    const float* Wq = (const float*)d_in[4];
    const float* bq = (const float*)d_in[5];
    const float* Wv = (const float*)d_in[6];
    const float* bv = (const float*)d_in[7];
    const float* W1 = (const float*)d_in[8];
    const float* b1 = (const float*)d_in[9];
    const float* W2 = (const float*)d_in[10];
    const float* b2 = (const float*)d_in[11];
    float* out = (float*)d_out;

    float *gx, *gz, *gf, *gb;
    u16 *xh, *xl, *hh, *hl, *zh, *zl, *wh, *wl, *kvh, *kvl;
    cudaGetSymbolAddress((void**)&gx, g_x);
    cudaGetSymbolAddress((void**)&gz, g_z);
    cudaGetSymbolAddress((void**)&gf, g_f);
    cudaGetSymbolAddress((void**)&gb, g_bqkv);
    cudaGetSymbolAddress((void**)&xh, g_xh);
    cudaGetSymbolAddress((void**)&xl, g_xl);
    cudaGetSymbolAddress((void**)&hh, g_hh);
    cudaGetSymbolAddress((void**)&hl, g_hl);
    cudaGetSymbolAddress((void**)&zh, g_zh);
    cudaGetSymbolAddress((void**)&zl, g_zl);
    cudaGetSymbolAddress((void**)&wh, g_wh);
    cudaGetSymbolAddress((void**)&wl, g_wl);
    cudaGetSymbolAddress((void**)&kvh, g_kqvh);
    cudaGetSymbolAddress((void**)&kvl, g_kqvl);

    cudaFuncSetAttribute((const void*)gemm_mma<true, 1, false>,
                         cudaFuncAttributeMaxDynamicSharedMemorySize, GEMM_SMEM);
    cudaFuncSetAttribute((const void*)gemm_mma<true, 0, false>,
                         cudaFuncAttributeMaxDynamicSharedMemorySize, GEMM_SMEM);
    cudaFuncSetAttribute((const void*)gemm_mma<false, 1, true>,
                         cudaFuncAttributeMaxDynamicSharedMemorySize, GEMM_SMEM);
    cudaFuncSetAttribute(attn_mma,
                         cudaFuncAttributeMaxDynamicSharedMemorySize, ATT_SMEM);

    const size_t O1 = 0;
    const size_t O2 = (size_t)FFD * DD;
    const size_t OK = 2 * (size_t)FFD * DD;

    prep_all<<<PREP_BLK, 256>>>(W1, W2, Wk, Wq, Wv, bk, bq, bv, wh, wl, gb);
    split_act<<<(NR * DD / 4 + 255) / 256, 256>>>(x, xh, xl, NR * DD / 4);

    const float* xin = x;
    for (int l = 0; l < NLAYERS; l++) {
        const size_t wb = (size_t)l * WPL;
        gemm_mma<true, 1, false><<<dim3(FFD / TILE_N, NR / TILE_M), 256, GEMM_SMEM>>>(
            xh, xl, wh + wb + O1, wl + wb + O1, b1 + (size_t)l * FFD,
            nullptr, hh, hl, NR, FFD, DD);
        gemm_mma<true, 0, false><<<dim3(DD / TILE_N, NR / TILE_M), 256, GEMM_SMEM>>>(
            hh, hl, wh + wb + O2, wl + wb + O2, b2 + (size_t)l * DD,
            gf, nullptr, nullptr, NR, DD, FFD);
        resnorm_kernel<true><<<NR, 256>>>(xin, gf, gz, zh, zl);
        gemm_mma<false, 1, true><<<dim3(3 * HD / TILE_N, NR / TILE_M), 256, GEMM_SMEM>>>(
            zh, zl, wh + wb + OK, wl + wb + OK, gb + (size_t)l * 3 * HD,
            nullptr, kvh, kvl, NR, 3 * HD, DD);
        attn_mma<<<dim3(TT / 64, BB * HH), 128, ATT_SMEM>>>(kvh, kvl, gf);
        if (l == NLAYERS - 1)
            resnorm_kernel<false><<<NR, 256>>>(gz, gf, out, nullptr, nullptr);
        else
            resnorm_kernel<true><<<NR, 256>>>(gz, gf, gx, xh, xl);
        xin = gx;
    }
}

// round 15
// speedup vs baseline: 1.5417x; 1.5417x over previous
#include <cuda_runtime.h>
#include <cuda_bf16.h>
#include <cstdint>
#include <math.h>

// ---------------------------------------------------------------------------
// TinyTransformer — fused 3-pass bf16-split mma GEMM (R12 pipeline: NSTG=5,
// CP_WAIT(2), 1 CTA/SM, modular slot indexing) + simplified-softmax mma
// attention with register-resident K. sm_103a.  [R12 best-known restore]
// ---------------------------------------------------------------------------

#define TT      1024
#define BB      4
#define DD      1024
#define HH      16
#define DQKV    64
#define FFD     4096
#define HD      1024
#define NR      4096
#define NLAYERS 4
#define EPSV    1e-6f

typedef unsigned short u16;
typedef unsigned int   u32;
typedef unsigned long long u64;

// ------------------------- scratch (no allocations) ------------------------
__device__ float g_x[(size_t)NR * DD];
__device__ float g_z[(size_t)NR * DD];
__device__ float g_f[(size_t)NR * DD];

__device__ u16 g_xh[(size_t)NR * DD], g_xl[(size_t)NR * DD];
__device__ u16 g_hh[(size_t)NR * FFD], g_hl[(size_t)NR * FFD];
__device__ u16 g_zh[(size_t)NR * DD], g_zl[(size_t)NR * DD];
__device__ u16 g_kqvh[(size_t)NR * 3 * HD], g_kqvl[(size_t)NR * 3 * HD];
__device__ float g_bqkv[(size_t)NLAYERS * 3 * HD];

#define WPL ((size_t)FFD * DD * 2 + (size_t)3 * HD * DD)
__device__ u16 g_wh[(size_t)NLAYERS * WPL];
__device__ u16 g_wl[(size_t)NLAYERS * WPL];

// ---------------------------- helpers --------------------------------------
__device__ __forceinline__ u32 smem_u32(const void* p) {
    u32 a;
    asm("{ .reg .u64 t; cvta.to.shared.u64 t, %1; cvt.u32.u64 %0, t; }"
        : "=r"(a) : "l"(p));
    return a;
}
__device__ __forceinline__ u16 bf_hi(float v) {
    return __bfloat16_as_ushort(__float2bfloat16(v));
}
__device__ __forceinline__ u16 bf_lo(float v, u16 hi) {
    float r = v - __bfloat162float(__ushort_as_bfloat16(hi));
    return __bfloat16_as_ushort(__float2bfloat16(r));
}
__device__ __forceinline__ u32 pk2(float a, float b) {
    __nv_bfloat162 t = __floats2bfloat162_rn(a, b);
    return *(u32*)&t;
}
__device__ __forceinline__ float pk_lo_f(u32 p) {
    return __bfloat162float(((__nv_bfloat162*)&p)->x);
}
__device__ __forceinline__ float pk_hi_f(u32 p) {
    return __bfloat162float(((__nv_bfloat162*)&p)->y);
}
__device__ __forceinline__ void cp16(u32 dst, const void* src) {
    asm volatile("cp.async.cg.shared.global [%0], [%1], 16;"
                 :: "r"(dst), "l"(src) : "memory");
}
#define CP_COMMIT() asm volatile("cp.async.commit_group;" ::: "memory")
#define CP_WAIT(n)  asm volatile("cp.async.wait_group %0;" :: "n"(n) : "memory")

__device__ __forceinline__ void ldsm4(u32* r, u32 a) {
    asm volatile("ldmatrix.sync.aligned.m8n8.x4.shared.b16 {%0,%1,%2,%3}, [%4];"
                 : "=r"(r[0]), "=r"(r[1]), "=r"(r[2]), "=r"(r[3]) : "r"(a));
}
__device__ __forceinline__ void ldsm4t(u32* r, u32 a) {
    asm volatile("ldmatrix.sync.aligned.m8n8.x4.trans.shared.b16 {%0,%1,%2,%3}, [%4];"
                 : "=r"(r[0]), "=r"(r[1]), "=r"(r[2]), "=r"(r[3]) : "r"(a));
}
__device__ __forceinline__ void mma_bf16(float* c, const u32* a, u32 b0, u32 b1) {
    asm volatile(
        "mma.sync.aligned.m16n8k16.row.col.f32.bf16.bf16.f32 "
        "{%0,%1,%2,%3}, {%4,%5,%6,%7}, {%8,%9}, {%0,%1,%2,%3};"
        : "+f"(c[0]), "+f"(c[1]), "+f"(c[2]), "+f"(c[3])
        : "r"(a[0]), "r"(a[1]), "r"(a[2]), "r"(a[3]), "r"(b0), "r"(b1));
}

// --------------------------- fused mma GEMM --------------------------------
// CTA 128x128, BK=32, 8 warps (2m x 4n), warp tile 64x32, 1 CTA/SM.
// NSTG=5, CP_WAIT(2): stages i and i+1 always resident (R9/R12 pipeline).
#define NSTG     5
#define TILE_M   128
#define TILE_N   128
#define TILE_K   32
#define TILE_SZ  (TILE_M * TILE_K * 2)    // 8 KB per operand tile
#define STAGE_SZ (4 * TILE_SZ)            // 32 KB: Ah|Al|Bh|Bl
#define EPI_PAD  132
#define GEMM_SMEM (NSTG * STAGE_SZ)       // 160 KB (> epi 67.6 KB)

__device__ __forceinline__ u32 tile_addr(u32 base, int r, int seg) {
    return base + r * 64 + ((seg ^ ((r >> 1) & 3)) << 4);
}

// MODE 0: fp32 C; MODE 1: bf16 hi/lo split. SCALEK: scale cols < HD by 1/32.
template <bool RELU, int MODE, bool SCALEK>
__global__ void __launch_bounds__(256, 1)
gemm_mma(const u16* __restrict__ Ah, const u16* __restrict__ Al,
         const u16* __restrict__ Bh, const u16* __restrict__ Bl,
         const float* __restrict__ bias,
         float* __restrict__ C, u16* __restrict__ Chi, u16* __restrict__ Clo,
         int M, int N, int K)
{
    extern __shared__ __align__(1024) char smem[];
    const u32 sbase = smem_u32(smem);

    const int tid = threadIdx.x;
    const int wid = tid >> 5, lane = tid & 31;
    const int wm = wid >> 2, wn = wid & 3;
    const int m0 = blockIdx.y * TILE_M;
    const int n0 = blockIdx.x * TILE_N;

    const int NITER = K / TILE_K;

    const int cr0 = tid >> 2, csg = tid & 3;
    const size_t gofs0 = (size_t)cr0 * K + csg * 8;
    const size_t gofs1 = gofs0 + (size_t)64 * K;
    const u32 sofs0 = tile_addr(0, cr0, csg);
    const u32 sofs1 = tile_addr(0, cr0 + 64, csg);

    auto load_stage = [&](int kc, int slot) {
        const u32 st = sbase + slot * STAGE_SZ;
        const size_t ab = (size_t)m0 * K + (size_t)kc * TILE_K;
        const size_t bb = (size_t)n0 * K + (size_t)kc * TILE_K;
        cp16(st + sofs0, Ah + ab + gofs0);
        cp16(st + sofs1, Ah + ab + gofs1);
        cp16(st + TILE_SZ + sofs0, Al + ab + gofs0);
        cp16(st + TILE_SZ + sofs1, Al + ab + gofs1);
        cp16(st + 2 * TILE_SZ + sofs0, Bh + bb + gofs0);
        cp16(st + 2 * TILE_SZ + sofs1, Bh + bb + gofs1);
        cp16(st + 3 * TILE_SZ + sofs0, Bl + bb + gofs0);
        cp16(st + 3 * TILE_SZ + sofs1, Bl + bb + gofs1);
        CP_COMMIT();
    };

    float acc[4][4][4];
#pragma unroll
    for (int i = 0; i < 4; i++)
#pragma unroll
        for (int j = 0; j < 4; j++)
#pragma unroll
            for (int t = 0; t < 4; t++) acc[i][j][t] = 0.f;

    const int lrow = lane & 15;
    const int lseg = lane >> 4;
    u32 aoff[2][4], boff[2][2];
#pragma unroll
    for (int ks = 0; ks < 2; ks++) {
#pragma unroll
        for (int ma = 0; ma < 4; ma++)
            aoff[ks][ma] = tile_addr(0, wm * 64 + ma * 16 + lrow, 2 * ks + lseg);
#pragma unroll
        for (int np = 0; np < 2; np++)
            boff[ks][np] = tile_addr(0, wn * 32 + np * 16 + lrow, 2 * ks + lseg);
    }

    u32 fah[2][4][4], fal[2][4][4], fbh[2][2][4], fbl[2][2][4];

    auto ldfrags = [&](int buf, u32 st, int ks) {
#pragma unroll
        for (int ma = 0; ma < 4; ma++) {
            ldsm4(fah[buf][ma], st + aoff[ks][ma]);
            ldsm4(fal[buf][ma], st + TILE_SZ + aoff[ks][ma]);
        }
#pragma unroll
        for (int np = 0; np < 2; np++) {
            ldsm4(fbh[buf][np], st + 2 * TILE_SZ + boff[ks][np]);
            ldsm4(fbl[buf][np], st + 3 * TILE_SZ + boff[ks][np]);
        }
    };
    auto mma_all = [&](int buf) {
#pragma unroll
        for (int ma = 0; ma < 4; ma++)
#pragma unroll
            for (int na = 0; na < 4; na++)
                mma_bf16(acc[ma][na], fah[buf][ma],
                         fbh[buf][na >> 1][na & 1], fbh[buf][na >> 1][(na & 1) + 2]);
#pragma unroll
        for (int ma = 0; ma < 4; ma++)
#pragma unroll
            for (int na = 0; na < 4; na++)
                mma_bf16(acc[ma][na], fah[buf][ma],
                         fbl[buf][na >> 1][na & 1], fbl[buf][na >> 1][(na & 1) + 2]);
#pragma unroll
        for (int ma = 0; ma < 4; ma++)
#pragma unroll
            for (int na = 0; na < 4; na++)
                mma_bf16(acc[ma][na], fal[buf][ma],
                         fbh[buf][na >> 1][na & 1], fbh[buf][na >> 1][(na & 1) + 2]);
    };

    for (int s = 0; s < NSTG - 1 && s < NITER; s++) load_stage(s, s);
    CP_WAIT(2);
    __syncthreads();
    ldfrags(0, sbase, 0);

    for (int i = 0; i < NITER; i++) {
        if (i + NSTG - 1 < NITER) load_stage(i + NSTG - 1, (i + NSTG - 1) % NSTG);

        const u32 stc = sbase + (i % NSTG) * STAGE_SZ;
        const u32 stn = sbase + ((i + 1) % NSTG) * STAGE_SZ;

        ldfrags(1, stc, 1);
        mma_all(0);
        if (i + 1 < NITER) ldfrags(0, stn, 0);
        mma_all(1);

        CP_WAIT(2);
        __syncthreads();
    }
    CP_WAIT(0);
    __syncthreads();

    // ---- epilogue ----
    float (*buf)[EPI_PAD] = (float (*)[EPI_PAD])smem;
    const int qr = lane >> 2, qc = (lane & 3) << 1;
#pragma unroll
    for (int ma = 0; ma < 4; ma++)
#pragma unroll
        for (int na = 0; na < 4; na++) {
            const int r = wm * 64 + ma * 16 + qr;
            const int c = wn * 32 + na * 8 + qc;
            buf[r][c]     = acc[ma][na][0];
            buf[r][c + 1] = acc[ma][na][1];
            buf[r + 8][c]     = acc[ma][na][2];
            buf[r + 8][c + 1] = acc[ma][na][3];
        }
    __syncthreads();

#pragma unroll
    for (int u = 0; u < 16; u++) {
        const int idx = tid + u * 256;
        const int r = idx >> 5, c4 = (idx & 31) << 2;
        const int col = n0 + c4;
        float4 v = *(float4*)&buf[r][c4];
        v.x += bias[col]; v.y += bias[col + 1];
        v.z += bias[col + 2]; v.w += bias[col + 3];
        if (RELU) {
            v.x = fmaxf(v.x, 0.f); v.y = fmaxf(v.y, 0.f);
            v.z = fmaxf(v.z, 0.f); v.w = fmaxf(v.w, 0.f);
        }
        if (SCALEK && col < HD) {
            v.x *= 0.03125f; v.y *= 0.03125f;
            v.z *= 0.03125f; v.w *= 0.03125f;
        }
        const size_t o = (size_t)(m0 + r) * N + col;
        if (MODE == 0) {
            *(float4*)(C + o) = v;
        } else {
            ushort4 hh4, ll4;
            hh4.x = bf_hi(v.x); ll4.x = bf_lo(v.x, hh4.x);
            hh4.y = bf_hi(v.y); ll4.y = bf_lo(v.y, hh4.y);
            hh4.z = bf_hi(v.z); ll4.z = bf_lo(v.z, hh4.z);
            hh4.w = bf_hi(v.w); ll4.w = bf_lo(v.w, hh4.w);
            *(ushort4*)(Chi + o) = hh4;
            *(ushort4*)(Clo + o) = ll4;
        }
    }
}

// --------------- prep: ALL weight transposes + bias pack (1 launch) --------
#define PREP_PL   11264
#define PREP_TRB  (NLAYERS * PREP_PL)
#define PREP_BLK  (PREP_TRB + 48)

__global__ void __launch_bounds__(256)
prep_all(const float* __restrict__ W1, const float* __restrict__ W2,
         const float* __restrict__ Wk, const float* __restrict__ Wq,
         const float* __restrict__ Wv,
         const float* __restrict__ bk, const float* __restrict__ bq,
         const float* __restrict__ bv,
         u16* __restrict__ wh, u16* __restrict__ wl, float* __restrict__ gb)
{
    const int bid = blockIdx.x;
    const int tid = threadIdx.x;

    if (bid >= PREP_TRB) {
        const int i = (bid - PREP_TRB) * 256 + tid;
        const int l = i / (3 * HD), c = i % (3 * HD);
        const float* s = (c < HD) ? bk : ((c < 2 * HD) ? bq : bv);
        gb[i] = s[l * HD + (c & (HD - 1))];
        return;
    }

    const int l = bid / PREP_PL;
    int t = bid % PREP_PL;
    const float* W;
    u16 *Th, *Tl;
    int K, N;
    const size_t wb = (size_t)l * WPL;
    if (t < 4096) {
        W = W1 + (size_t)l * DD * FFD; K = DD; N = FFD;
        Th = wh + wb; Tl = wl + wb;
    } else if (t < 8192) {
        t -= 4096;
        W = W2 + (size_t)l * FFD * DD; K = FFD; N = DD;
        Th = wh + wb + (size_t)FFD * DD; Tl = wl + wb + (size_t)FFD * DD;
    } else {
        t -= 8192;
        const int m = t >> 10; t &= 1023;
        const float* Wm = (m == 0) ? Wk : ((m == 1) ? Wq : Wv);
        W = Wm + (size_t)l * DD * HD; K = DD; N = HD;
        const size_t o = 2 * (size_t)FFD * DD + (size_t)m * HD * DD;
        Th = wh + wb + o; Tl = wl + wb + o;
    }
    const int nx = N >> 5;
    const int n0 = (t % nx) << 5, k0 = (t / nx) << 5;

    __shared__ float tb[32][33];
    const int tx = tid & 31, ty = tid >> 5;
#pragma unroll
    for (int i = 0; i < 4; i++)
        tb[ty + i * 8][tx] = W[(size_t)(k0 + ty + i * 8) * N + n0 + tx];
    __syncthreads();

    const int n = tid >> 3;
    const int kk = (tid & 7) << 2;
    u16 hx[4], lx[4];
#pragma unroll
    for (int j = 0; j < 4; j++) {
        const float v = tb[kk + j][n];
        hx[j] = bf_hi(v);
        lx[j] = bf_lo(v, hx[j]);
    }
    const size_t o = (size_t)(n0 + n) * K + k0 + kk;
    *(ushort4*)(Th + o) = make_ushort4(hx[0], hx[1], hx[2], hx[3]);
    *(ushort4*)(Tl + o) = make_ushort4(lx[0], lx[1], lx[2], lx[3]);
}

__global__ void __launch_bounds__(256)
split_act(const float* __restrict__ X, u16* __restrict__ Xh,
          u16* __restrict__ Xl, int n4)
{
    const int i = blockIdx.x * 256 + threadIdx.x;
    if (i >= n4) return;
    const float4 v = ((const float4*)X)[i];
    ushort4 h, l;
    h.x = bf_hi(v.x); l.x = bf_lo(v.x, h.x);
    h.y = bf_hi(v.y); l.y = bf_lo(v.y, h.y);
    h.z = bf_hi(v.z); l.z = bf_lo(v.z, h.z);
    h.w = bf_hi(v.w); l.w = bf_lo(v.w, h.w);
    ((ushort4*)Xh)[i] = h;
    ((ushort4*)Xl)[i] = l;
}

// ------------------------------ resnorm ------------------------------------
template <bool SPLIT>
__global__ void __launch_bounds__(256)
resnorm_kernel(const float* __restrict__ X, const float* __restrict__ FX,
               float* __restrict__ OUT, u16* __restrict__ Oh, u16* __restrict__ Ol)
{
    __shared__ float red[8], red2[8], stat[2];
    const int tid = threadIdx.x;
    const int w = tid >> 5, lane = tid & 31;
    const size_t off = (size_t)blockIdx.x * DD;

    const float4 xv = ((const float4*)(X + off))[tid];
    const float4 fv = ((const float4*)(FX + off))[tid];
    const float y0 = xv.x + fv.x, y1 = xv.y + fv.y;
    const float y2 = xv.z + fv.z, y3 = xv.w + fv.w;

    float s = y0 + y1 + y2 + y3;
    float sq = y0 * y0 + y1 * y1 + y2 * y2 + y3 * y3;
#pragma unroll
    for (int o = 16; o; o >>= 1) {
        s += __shfl_xor_sync(0xFFFFFFFFu, s, o);
        sq += __shfl_xor_sync(0xFFFFFFFFu, sq, o);
    }
    if (lane == 0) { red[w] = s; red2[w] = sq; }
    __syncthreads();
    if (tid == 0) {
        float S = 0.f, Q = 0.f;
#pragma unroll
        for (int i = 0; i < 8; i++) { S += red[i]; Q += red2[i]; }
        const float mu = S * (1.0f / DD);
        const float var = fmaxf((Q - (float)DD * mu * mu) * (1.0f / (DD - 1)), 0.0f);
        stat[0] = mu;
        stat[1] = 1.0f / (sqrtf(var) + EPSV);
    }
    __syncthreads();
    const float mu = stat[0], inv = stat[1];
    const float4 o = make_float4((y0 - mu) * inv, (y1 - mu) * inv,
                                 (y2 - mu) * inv, (y3 - mu) * inv);
    ((float4*)(OUT + off))[tid] = o;
    if (SPLIT) {
        ushort4 h, l;
        h.x = bf_hi(o.x); l.x = bf_lo(o.x, h.x);
        h.y = bf_hi(o.y); l.y = bf_lo(o.y, h.y);
        h.z = bf_hi(o.z); l.z = bf_lo(o.z, h.z);
        h.w = bf_hi(o.w); l.w = bf_lo(o.w, h.w);
        ((ushort4*)(Oh + off))[tid] = h;
        ((ushort4*)(Ol + off))[tid] = l;
    }
}

// ----------------------- mma flash attention --------------------------------
#define ASTR  72
#define ATSZ  (64 * ASTR)
#define ATT_SMEM ((2 + 8) * ATSZ * 2)

__global__ void __launch_bounds__(128, 2)
attn_mma(const u16* __restrict__ kqvh, const u16* __restrict__ kqvl,
         float* __restrict__ Ob)
{
    extern __shared__ __align__(128) u16 asm_[];
    u16* Kh = asm_;
    u16* Kl = asm_ + ATSZ;
    u16* stg = asm_ + 2 * ATSZ;

    const int tid = threadIdx.x;
    const int wid = tid >> 5, lane = tid & 31;
    const int bh = blockIdx.y;
    const int b = bh >> 4, h = bh & 15;
    const int i0 = blockIdx.x * 64;
    const int colK = h * DQKV;

#pragma unroll
    for (int k = 0; k < 8; k++) {
        const int c = tid + k * 128;
        const int hi = (c < 512);
        const int idx = c & 511;
        const int r = idx >> 3, ch = idx & 7;
        const u16* src = (hi ? kqvh : kqvl) +
                         (size_t)((i0 + r) * BB + b) * (3 * HD) + colK + ch * 8;
        u16* dst = (hi ? Kh : Kl) + r * ASTR + ch * 8;
        cp16(smem_u32(dst), src);
    }

    auto load_stage = [&](int j0, int s) {
        u16* base = stg + s * 4 * ATSZ;
#pragma unroll
        for (int k = 0; k < 16; k++) {
            const int c = tid + k * 128;
            const int sel = c >> 9;
            const int idx = c & 511;
            const int r = idx >> 3, ch = idx & 7;
            const u16* sp = (sel & 1) ? kqvl : kqvh;
            const int cb = (sel >> 1) ? 2 * HD : HD;
            cp16(smem_u32(base + sel * ATSZ + r * ASTR + ch * 8),
                 sp + (size_t)((j0 + r) * BB + b) * (3 * HD) + cb + colK + ch * 8);
        }
    };

    load_stage(0, 0);
    CP_COMMIT();

    float l0 = 0.f, l1 = 0.f;
    float o[8][4];
#pragma unroll
    for (int a = 0; a < 8; a++)
#pragma unroll
        for (int q = 0; q < 4; q++) o[a][q] = 0.f;

    const int r16 = lane & 15;
    const int kh8 = (lane >> 4) << 3;
    const int g = lane >> 3;
    const int vrow = ((g & 1) << 3) + (lane & 7);
    const int vcol = (g >> 1) << 3;

    u32 kfh[4][4], kfl[4][4];

    for (int jt = 0; jt < TT / 64; jt++) {
        if (jt + 1 < TT / 64) {
            load_stage((jt + 1) * 64, (jt + 1) & 1);
            CP_COMMIT();
            CP_WAIT(1);
        } else {
            CP_WAIT(0);
        }
        __syncthreads();

        if (jt == 0) {
#pragma unroll
            for (int t = 0; t < 4; t++) {
                ldsm4(kfh[t], smem_u32(Kh + (wid * 16 + r16) * ASTR + t * 16 + kh8));
                ldsm4(kfl[t], smem_u32(Kl + (wid * 16 + r16) * ASTR + t * 16 + kh8));
            }
        }

        u16* sb = stg + (jt & 1) * 4 * ATSZ;
        u16* Qh = sb;
        u16* Ql = sb + ATSZ;
        u16* Vh = sb + 2 * ATSZ;
        u16* Vl = sb + 3 * ATSZ;

        float sc[8][4];
#pragma unroll
        for (int a = 0; a < 8; a++)
#pragma unroll
            for (int q = 0; q < 4; q++) sc[a][q] = 0.f;

#pragma unroll
        for (int t = 0; t < 4; t++) {
#pragma unroll
            for (int jb = 0; jb < 4; jb++) {
                u32 qh[4], ql[4];
                ldsm4(qh, smem_u32(Qh + (jb * 16 + r16) * ASTR + t * 16 + kh8));
                ldsm4(ql, smem_u32(Ql + (jb * 16 + r16) * ASTR + t * 16 + kh8));
#pragma unroll
                for (int sel = 0; sel < 2; sel++) {
                    const int a = jb * 2 + sel;
                    mma_bf16(sc[a], kfh[t], qh[sel], qh[sel + 2]);
                    mma_bf16(sc[a], kfl[t], qh[sel], qh[sel + 2]);
                    mma_bf16(sc[a], kfh[t], ql[sel], ql[sel + 2]);
                }
            }
        }

        float ps0 = 0.f, ps1 = 0.f;
#pragma unroll
        for (int a = 0; a < 8; a++) {
            sc[a][0] = __expf(sc[a][0]); ps0 += sc[a][0];
            sc[a][1] = __expf(sc[a][1]); ps0 += sc[a][1];
            sc[a][2] = __expf(sc[a][2]); ps1 += sc[a][2];
            sc[a][3] = __expf(sc[a][3]); ps1 += sc[a][3];
        }
        ps0 += __shfl_xor_sync(0xFFFFFFFFu, ps0, 1);
        ps0 += __shfl_xor_sync(0xFFFFFFFFu, ps0, 2);
        ps1 += __shfl_xor_sync(0xFFFFFFFFu, ps1, 1);
        ps1 += __shfl_xor_sync(0xFFFFFFFFu, ps1, 2);
        l0 += ps0;
        l1 += ps1;

#pragma unroll
        for (int t = 0; t < 4; t++) {
            u32 ph[4], pl[4];
            ph[0] = pk2(sc[2 * t][0], sc[2 * t][1]);
            ph[1] = pk2(sc[2 * t][2], sc[2 * t][3]);
            ph[2] = pk2(sc[2 * t + 1][0], sc[2 * t + 1][1]);
            ph[3] = pk2(sc[2 * t + 1][2], sc[2 * t + 1][3]);
            pl[0] = pk2(sc[2 * t][0] - pk_lo_f(ph[0]), sc[2 * t][1] - pk_hi_f(ph[0]));
            pl[1] = pk2(sc[2 * t][2] - pk_lo_f(ph[1]), sc[2 * t][3] - pk_hi_f(ph[1]));
            pl[2] = pk2(sc[2 * t + 1][0] - pk_lo_f(ph[2]), sc[2 * t + 1][1] - pk_hi_f(ph[2]));
            pl[3] = pk2(sc[2 * t + 1][2] - pk_lo_f(ph[3]), sc[2 * t + 1][3] - pk_hi_f(ph[3]));
#pragma unroll
            for (int dq = 0; dq < 4; dq++) {
                u32 vh4[4], vl4[4];
                const u32 va = (t * 16 + vrow) * ASTR + dq * 16 + vcol;
                ldsm4t(vh4, smem_u32(Vh + va));
                ldsm4t(vl4, smem_u32(Vl + va));
#pragma unroll
                for (int sel = 0; sel < 2; sel++) {
                    const int a = dq * 2 + sel;
                    mma_bf16(o[a], ph, vh4[2 * sel], vh4[2 * sel + 1]);
                    mma_bf16(o[a], pl, vh4[2 * sel], vh4[2 * sel + 1]);
                    mma_bf16(o[a], ph, vl4[2 * sel], vl4[2 * sel + 1]);
                }
            }
        }
        __syncthreads();
    }

    const float inv0 = 1.0f / l0, inv1 = 1.0f / l1;
    const int lr = lane >> 2;
    const int row0 = i0 + wid * 16 + lr;
#pragma unroll
    for (int a = 0; a < 8; a++) {
        const int d = a * 8 + ((lane & 3) << 1);
        const size_t o0 = (size_t)(row0 * BB + b) * HD + colK + d;
        const size_t o1 = (size_t)((row0 + 8) * BB + b) * HD + colK + d;
        *(float2*)(Ob + o0) = make_float2(o[a][0] * inv0, o[a][1] * inv0);
        *(float2*)(Ob + o1) = make_float2(o[a][2] * inv1, o[a][3] * inv1);
    }
}

// ----------------------------- launcher ------------------------------------
extern "C" void kernel_launch(void* const* d_in, const int* in_sizes, int n_in,
                              void* d_out, int out_size)
{
    (void)in_sizes; (void)n_in; (void)out_size;
    const float* x  = (const float*)d_in[0];
    const float* Wk = (const float*)d_in[2];
    const float* bk = (const float*)d_in[3];
    const float* Wq = (const float*)d_in[4];
    const float* bq = (const float*)d_in[5];
    const float* Wv = (const float*)d_in[6];
    const float* bv = (const float*)d_in[7];
    const float* W1 = (const float*)d_in[8];
    const float* b1 = (const float*)d_in[9];
    const float* W2 = (const float*)d_in[10];
    const float* b2 = (const float*)d_in[11];
    float* out = (float*)d_out;

    float *gx, *gz, *gf, *gb;
    u16 *xh, *xl, *hh, *hl, *zh, *zl, *wh, *wl, *kvh, *kvl;
    cudaGetSymbolAddress((void**)&gx, g_x);
    cudaGetSymbolAddress((void**)&gz, g_z);
    cudaGetSymbolAddress((void**)&gf, g_f);
    cudaGetSymbolAddress((void**)&gb, g_bqkv);
    cudaGetSymbolAddress((void**)&xh, g_xh);
    cudaGetSymbolAddress((void**)&xl, g_xl);
    cudaGetSymbolAddress((void**)&hh, g_hh);
    cudaGetSymbolAddress((void**)&hl, g_hl);
    cudaGetSymbolAddress((void**)&zh, g_zh);
    cudaGetSymbolAddress((void**)&zl, g_zl);
    cudaGetSymbolAddress((void**)&wh, g_wh);
    cudaGetSymbolAddress((void**)&wl, g_wl);
    cudaGetSymbolAddress((void**)&kvh, g_kqvh);
    cudaGetSymbolAddress((void**)&kvl, g_kqvl);

    cudaFuncSetAttribute((const void*)gemm_mma<true, 1, false>,
                         cudaFuncAttributeMaxDynamicSharedMemorySize, GEMM_SMEM);
    cudaFuncSetAttribute((const void*)gemm_mma<true, 0, false>,
                         cudaFuncAttributeMaxDynamicSharedMemorySize, GEMM_SMEM);
    cudaFuncSetAttribute((const void*)gemm_mma<false, 1, true>,
                         cudaFuncAttributeMaxDynamicSharedMemorySize, GEMM_SMEM);
    cudaFuncSetAttribute(attn_mma,
                         cudaFuncAttributeMaxDynamicSharedMemorySize, ATT_SMEM);

    const size_t O1 = 0;
    const size_t O2 = (size_t)FFD * DD;
    const size_t OK = 2 * (size_t)FFD * DD;

    prep_all<<<PREP_BLK, 256>>>(W1, W2, Wk, Wq, Wv, bk, bq, bv, wh, wl, gb);
    split_act<<<(NR * DD / 4 + 255) / 256, 256>>>(x, xh, xl, NR * DD / 4);

    const float* xin = x;
    for (int l = 0; l < NLAYERS; l++) {
        const size_t wb = (size_t)l * WPL;
        gemm_mma<true, 1, false><<<dim3(FFD / TILE_N, NR / TILE_M), 256, GEMM_SMEM>>>(
            xh, xl, wh + wb + O1, wl + wb + O1, b1 + (size_t)l * FFD,
            nullptr, hh, hl, NR, FFD, DD);
        gemm_mma<true, 0, false><<<dim3(DD / TILE_N, NR / TILE_M), 256, GEMM_SMEM>>>(
            hh, hl, wh + wb + O2, wl + wb + O2, b2 + (size_t)l * DD,
            gf, nullptr, nullptr, NR, DD, FFD);
        resnorm_kernel<true><<<NR, 256>>>(xin, gf, gz, zh, zl);
        gemm_mma<false, 1, true><<<dim3(3 * HD / TILE_N, NR / TILE_M), 256, GEMM_SMEM>>>(
            zh, zl, wh + wb + OK, wl + wb + OK, gb + (size_t)l * 3 * HD,
            nullptr, kvh, kvl, NR, 3 * HD, DD);
        attn_mma<<<dim3(TT / 64, BB * HH), 128, ATT_SMEM>>>(kvh, kvl, gf);
        if (l == NLAYERS - 1)
            resnorm_kernel<false><<<NR, 256>>>(gz, gf, out, nullptr, nullptr);
        else
            resnorm_kernel<true><<<NR, 256>>>(gz, gf, gx, xh, xl);
        xin = gx;
    }
}